// round 11
// baseline (speedup 1.0000x reference)
#include <cuda_runtime.h>
#include <cuda_bf16.h>

// Problem constants
#define Hc 200          // H
#define Wc 196          // W
#define NPIX (Hc * Wc)  // 39200 pixels per camera
#define NCH 256
#define NCAM 6
#define SSZ 400
#define NCELL (SSZ * SSZ)    // 160000

// Scratch (allocation-free rule). Zero at module load; finalize re-zeros after
// reading, so the grids are zero at every kernel_launch entry (correctness run
// and every graph replay).
__device__ float g_sum[NCELL];
__device__ float g_cnt[NCELL];

// R2-shape main kernel: one thread per (cam, pixel), 256-thread blocks,
// scalar LDG.32 streaming. Measured best per-byte config across R2..R8
// (~5.6 TB/s vs ~5.2 for 128-thr / float4 variants).
// Mask read as 32-bit word: correct for int32 AND float32 bool storage
// (true nonzero in both); u8 storage ruled out empirically in R1.
__global__ __launch_bounds__(256) void bev_dot_scatter_kernel(
    const float* __restrict__ feats,   // [NCAM, NCH, Wc, Hc]
    const float* __restrict__ mats,    // [NCAM, 4, 4]
    const float* __restrict__ lc,      // [4, NPIX], n = h*W + w
    const int*   __restrict__ mask,    // [NPIX]
    const float* __restrict__ w_cls)   // [NCH]
{
    __shared__ float sw[NCH];
    __shared__ float sm[8];  // rows 0,1 of this cam's 4x4

    const int tid = threadIdx.x;
    const int cam = blockIdx.y;

    sw[tid] = w_cls[tid];
    if (tid < 8) sm[tid] = mats[cam * 16 + tid];
    __syncthreads();

    const int pix = blockIdx.x * 256 + tid;
    if (pix >= NPIX) return;

    const float* p = feats + (size_t)cam * NCH * NPIX + pix;

    float a0 = 0.f, a1 = 0.f, a2 = 0.f, a3 = 0.f;
#pragma unroll 8
    for (int ch = 0; ch < NCH; ch += 4) {
        a0 = fmaf(p[(ch + 0) * NPIX], sw[ch + 0], a0);
        a1 = fmaf(p[(ch + 1) * NPIX], sw[ch + 1], a1);
        a2 = fmaf(p[(ch + 2) * NPIX], sw[ch + 2], a2);
        a3 = fmaf(p[(ch + 3) * NPIX], sw[ch + 3], a3);
    }
    const float dot = (a0 + a1) + (a2 + a3);

    // pix = w*H + h ; logical flat index n = h*W + w
    const int wq = pix / Hc;
    const int h  = pix - wq * Hc;
    const int n  = h * Wc + wq;

    if (mask[n] != 0) {
        const float gx = lc[n];
        const float gy = lc[NPIX + n];
        const float x = sm[0] * gx + sm[1] * gy + sm[3];
        const float y = sm[4] * gx + sm[5] * gy + sm[7];
        // (coord + 100) / 0.5 == (coord + 100) * 2 exactly; jnp.round == rintf
        const float fx = rintf((x + 100.0f) * 2.0f);
        const float fy = rintf((y + 100.0f) * 2.0f);
        if (fx >= 0.0f && fx < (float)SSZ && fy >= 0.0f && fy < (float)SSZ) {
            const int cell = (int)fx * SSZ + (int)fy;
            atomicAdd(&g_sum[cell], dot);
            atomicAdd(&g_cnt[cell], 1.0f);
        }
    }
}

// Finalize AND restore scratch to zero for the next run (graph replay invariant).
__global__ __launch_bounds__(256) void finalize_kernel(float* __restrict__ out,
                                                       const float* __restrict__ b_cls) {
    int i4 = blockIdx.x * 256 + threadIdx.x;
    if (i4 >= NCELL / 4) return;
    float4* s4 = (float4*)g_sum + i4;
    float4* c4 = (float4*)g_cnt + i4;
    float4 s = *s4;
    float4 c = *c4;
    const float b = b_cls[0];
    float4 o;
    // where(cnt>=1, sum/max(cnt,1), sum) == sum/max(cnt,1): sum==0 when cnt==0
    o.x = s.x / fmaxf(c.x, 1.0f) + b;
    o.y = s.y / fmaxf(c.y, 1.0f) + b;
    o.z = s.z / fmaxf(c.z, 1.0f) + b;
    o.w = s.w / fmaxf(c.w, 1.0f) + b;
    ((float4*)out)[i4] = o;
    float4 z = make_float4(0.f, 0.f, 0.f, 0.f);
    *s4 = z;
    *c4 = z;
}

// Profiling-alignment nop: with 3 launches per call the fixed ncu capture
// (-s 5 -c 1) lands on the FIRST kernel of a call (observed R3/R4), i.e. the
// main kernel. Deterministic, touches nothing.
__global__ void nop_kernel() {}

extern "C" void kernel_launch(void* const* d_in, const int* in_sizes, int n_in,
                              void* d_out, int out_size) {
    // Resolve inputs by element count (all distinct) — robust to metadata order.
    const float* feats = 0; const float* mats = 0; const float* lc = 0;
    const int*   mask  = 0; const float* w_cls = 0; const float* b_cls = 0;
    for (int i = 0; i < n_in; i++) {
        switch (in_sizes[i]) {
            case 60211200: feats = (const float*)d_in[i]; break;
            case 96:       mats  = (const float*)d_in[i]; break;
            case 156800:   lc    = (const float*)d_in[i]; break;
            case 39200:    mask  = (const int*)d_in[i];   break;
            case 256:      w_cls = (const float*)d_in[i]; break;
            case 1:        b_cls = (const float*)d_in[i]; break;
        }
    }
    float* out = (float*)d_out;

    dim3 grid((NPIX + 255) / 256, NCAM);   // 154 x 6 = 924 blocks
    bev_dot_scatter_kernel<<<grid, 256>>>(feats, mats, lc, mask, w_cls);

    finalize_kernel<<<(NCELL / 4 + 255) / 256, 256>>>(out, b_cls);

    nop_kernel<<<1, 32>>>();
}

// round 12
// speedup vs baseline: 1.1876x; 1.1876x over previous
#include <cuda_runtime.h>
#include <cuda_bf16.h>

// Problem constants
#define Hc 200          // H
#define Wc 196          // W
#define NPIX (Hc * Wc)  // 39200 pixels per camera
#define NCH 256
#define NCHUNK 2
#define CHCH (NCH / NCHUNK)  // 128 channels per chunk
#define NCAM 6
#define SSZ 400
#define NCELL (SSZ * SSZ)    // 160000

// Scratch (allocation-free rule). Zero at module load; finalize re-zeros after
// reading, so the grids are zero at every kernel_launch entry (correctness run
// and every graph replay).
__device__ float g_sum[NCELL];
__device__ float g_cnt[NCELL];

// Main kernel: one thread per (cam, pixel, channel-chunk). Scalar LDG.32
// streaming (each warp instruction = one 128B line). Channel-chunking x2
// (grid z) doubles resident warps: 1848 blocks x 256thr, regs forced <=32 so
// 8 blocks = 64 warps/SM fit -> more loads in flight (R9 profile showed
// DRAM 60%, issue 18%: latency-bound, not ceiling-bound).
// Partial dots are atomically accumulated (scatter-add is linear in channels);
// chunk 0 adds the count. Mask read as 32-bit word: correct for int32 AND
// float32 bool storage; u8 ruled out empirically in R1.
// The meshgrid coords are computed analytically (exact linspace replication
// in double) - kills the uncoalesced lc gather.
__global__ __launch_bounds__(256, 8) void bev_dot_scatter_kernel(
    const float* __restrict__ feats,   // [NCAM, NCH, Wc, Hc]
    const float* __restrict__ mats,    // [NCAM, 4, 4]
    const int*   __restrict__ mask,    // [NPIX], n = h*W + w
    const float* __restrict__ w_cls)   // [NCH]
{
    __shared__ float sw[CHCH];
    __shared__ float sm[8];  // rows 0,1 of this cam's 4x4

    const int tid   = threadIdx.x;
    const int cam   = blockIdx.y;
    const int chunk = blockIdx.z;

    if (tid < CHCH) sw[tid] = w_cls[chunk * CHCH + tid];
    if (tid < 8)    sm[tid] = mats[cam * 16 + tid];
    __syncthreads();

    const int pix = blockIdx.x * 256 + tid;
    if (pix >= NPIX) return;

    const float* p = feats + (size_t)cam * NCH * NPIX
                   + (size_t)chunk * CHCH * NPIX + pix;

    float a0 = 0.f, a1 = 0.f, a2 = 0.f, a3 = 0.f;
#pragma unroll 8
    for (int ch = 0; ch < CHCH; ch += 4) {
        a0 = fmaf(p[(ch + 0) * NPIX], sw[ch + 0], a0);
        a1 = fmaf(p[(ch + 1) * NPIX], sw[ch + 1], a1);
        a2 = fmaf(p[(ch + 2) * NPIX], sw[ch + 2], a2);
        a3 = fmaf(p[(ch + 3) * NPIX], sw[ch + 3], a3);
    }
    const float dot = (a0 + a1) + (a2 + a3);

    // pix = w*H + h ; logical flat index n = h*W + w
    const int wq = pix / Hc;
    const int h  = pix - wq * Hc;
    const int n  = h * Wc + wq;

    if (mask[n] != 0) {
        // Exact np.linspace replication (float64 accumulate, cast to f32):
        // xs = linspace(-25,25,200)[h], ys = linspace(1,50,196)[w]
        const float gx = (float)(-25.0 + (double)h * (50.0 / 199.0));
        const float gy = (float)(  1.0 + (double)wq * (49.0 / 195.0));
        const float x = sm[0] * gx + sm[1] * gy + sm[3];
        const float y = sm[4] * gx + sm[5] * gy + sm[7];
        // (coord + 100) / 0.5 == (coord + 100) * 2 exactly; jnp.round == rintf
        const float fx = rintf((x + 100.0f) * 2.0f);
        const float fy = rintf((y + 100.0f) * 2.0f);
        if (fx >= 0.0f && fx < (float)SSZ && fy >= 0.0f && fy < (float)SSZ) {
            const int cell = (int)fx * SSZ + (int)fy;
            atomicAdd(&g_sum[cell], dot);
            if (chunk == 0) atomicAdd(&g_cnt[cell], 1.0f);
        }
    }
}

// Finalize AND restore scratch to zero for the next run (graph replay invariant).
__global__ __launch_bounds__(256) void finalize_kernel(float* __restrict__ out,
                                                       const float* __restrict__ b_cls) {
    int i4 = blockIdx.x * 256 + threadIdx.x;
    if (i4 >= NCELL / 4) return;
    float4* s4 = (float4*)g_sum + i4;
    float4* c4 = (float4*)g_cnt + i4;
    float4 s = *s4;
    float4 c = *c4;
    const float b = b_cls[0];
    float4 o;
    // where(cnt>=1, sum/max(cnt,1), sum) == sum/max(cnt,1): sum==0 when cnt==0
    o.x = s.x / fmaxf(c.x, 1.0f) + b;
    o.y = s.y / fmaxf(c.y, 1.0f) + b;
    o.z = s.z / fmaxf(c.z, 1.0f) + b;
    o.w = s.w / fmaxf(c.w, 1.0f) + b;
    ((float4*)out)[i4] = o;
    float4 z = make_float4(0.f, 0.f, 0.f, 0.f);
    *s4 = z;
    *c4 = z;
}

// Profiling-alignment nop: with 3 launches per call the fixed ncu capture
// (-s 5 -c 1) lands on the FIRST kernel of a call (verified R9), i.e. main.
__global__ void nop_kernel() {}

extern "C" void kernel_launch(void* const* d_in, const int* in_sizes, int n_in,
                              void* d_out, int out_size) {
    // Resolve inputs by element count (all distinct) — robust to metadata order.
    const float* feats = 0; const float* mats = 0;
    const int*   mask  = 0; const float* w_cls = 0; const float* b_cls = 0;
    for (int i = 0; i < n_in; i++) {
        switch (in_sizes[i]) {
            case 60211200: feats = (const float*)d_in[i]; break;
            case 96:       mats  = (const float*)d_in[i]; break;
            case 39200:    mask  = (const int*)d_in[i];   break;
            case 256:      w_cls = (const float*)d_in[i]; break;
            case 1:        b_cls = (const float*)d_in[i]; break;
            default: break;  // 156800 (lc) unused: meshgrid computed analytically
        }
    }
    float* out = (float*)d_out;

    dim3 grid((NPIX + 255) / 256, NCAM, NCHUNK);  // 154 x 6 x 2 = 1848 blocks
    bev_dot_scatter_kernel<<<grid, 256>>>(feats, mats, mask, w_cls);

    finalize_kernel<<<(NCELL / 4 + 255) / 256, 256>>>(out, b_cls);

    nop_kernel<<<1, 32>>>();
}

// round 14
// speedup vs baseline: 1.2219x; 1.0289x over previous
#include <cuda_runtime.h>
#include <cuda_bf16.h>

// Problem constants
#define Hc 200          // H
#define Wc 196          // W
#define NPIX (Hc * Wc)  // 39200 pixels per camera
#define NCH 256
#define NCHUNK 4
#define CHCH (NCH / NCHUNK)  // 64 channels per chunk
#define NCAM 6
#define SSZ 400
#define NCELL (SSZ * SSZ)    // 160000

// Scratch (allocation-free rule). Zero at module load; finalize re-zeros after
// reading, so the grids are zero at every kernel_launch entry (correctness run
// and every graph replay).
__device__ float g_sum[NCELL];
__device__ float g_cnt[NCELL];

// Main kernel: one thread per (cam, pixel, channel-chunk). Scalar LDG.32
// streaming (each warp instruction = one 128B line). NCHUNK=4 gives 3696
// tiles -> ~25 tiles/SM: tile quantization 0.1% (vs 4% at NCHUNK=2) and a
// ~1.7us drain tail. regs forced <=32 so 8 blocks = 64 warps/SM stay
// resident (R11 profile: DRAM 72%, occ 81% -> tail/ramp bound).
// Partial dots accumulate atomically (scatter-add is linear in channels);
// chunk 0 adds the count. Mask read as 32-bit word: correct for int32 AND
// float32 bool storage; u8 ruled out empirically in R1. Meshgrid computed
// analytically (exact np.linspace replication in double).
__global__ __launch_bounds__(256, 8) void bev_dot_scatter_kernel(
    const float* __restrict__ feats,   // [NCAM, NCH, Wc, Hc]
    const float* __restrict__ mats,    // [NCAM, 4, 4]
    const int*   __restrict__ mask,    // [NPIX], n = h*W + w
    const float* __restrict__ w_cls)   // [NCH]
{
    __shared__ float sw[CHCH];
    __shared__ float sm[8];  // rows 0,1 of this cam's 4x4

    const int tid   = threadIdx.x;
    const int cam   = blockIdx.y;
    const int chunk = blockIdx.z;

    if (tid < CHCH) sw[tid] = w_cls[chunk * CHCH + tid];
    if (tid < 8)    sm[tid] = mats[cam * 16 + tid];
    __syncthreads();

    const int pix = blockIdx.x * 256 + tid;
    if (pix >= NPIX) return;

    const float* p = feats + (size_t)cam * NCH * NPIX
                   + (size_t)chunk * CHCH * NPIX + pix;

    float a0 = 0.f, a1 = 0.f, a2 = 0.f, a3 = 0.f;
#pragma unroll 8
    for (int ch = 0; ch < CHCH; ch += 4) {
        a0 = fmaf(p[(ch + 0) * NPIX], sw[ch + 0], a0);
        a1 = fmaf(p[(ch + 1) * NPIX], sw[ch + 1], a1);
        a2 = fmaf(p[(ch + 2) * NPIX], sw[ch + 2], a2);
        a3 = fmaf(p[(ch + 3) * NPIX], sw[ch + 3], a3);
    }
    const float dot = (a0 + a1) + (a2 + a3);

    // pix = w*H + h ; logical flat index n = h*W + w
    const int wq = pix / Hc;
    const int h  = pix - wq * Hc;
    const int n  = h * Wc + wq;

    if (mask[n] != 0) {
        // xs = linspace(-25,25,200)[h], ys = linspace(1,50,196)[w]
        const float gx = (float)(-25.0 + (double)h * (50.0 / 199.0));
        const float gy = (float)(  1.0 + (double)wq * (49.0 / 195.0));
        const float x = sm[0] * gx + sm[1] * gy + sm[3];
        const float y = sm[4] * gx + sm[5] * gy + sm[7];
        // (coord + 100) / 0.5 == (coord + 100) * 2 exactly; jnp.round == rintf
        const float fx = rintf((x + 100.0f) * 2.0f);
        const float fy = rintf((y + 100.0f) * 2.0f);
        if (fx >= 0.0f && fx < (float)SSZ && fy >= 0.0f && fy < (float)SSZ) {
            const int cell = (int)fx * SSZ + (int)fy;
            atomicAdd(&g_sum[cell], dot);
            if (chunk == 0) atomicAdd(&g_cnt[cell], 1.0f);
        }
    }
}

// Finalize AND restore scratch to zero for the next run (graph replay invariant).
__global__ __launch_bounds__(256) void finalize_kernel(float* __restrict__ out,
                                                       const float* __restrict__ b_cls) {
    int i4 = blockIdx.x * 256 + threadIdx.x;
    if (i4 >= NCELL / 4) return;
    float4* s4 = (float4*)g_sum + i4;
    float4* c4 = (float4*)g_cnt + i4;
    float4 s = *s4;
    float4 c = *c4;
    const float b = b_cls[0];
    float4 o;
    // where(cnt>=1, sum/max(cnt,1), sum) == sum/max(cnt,1): sum==0 when cnt==0
    o.x = s.x / fmaxf(c.x, 1.0f) + b;
    o.y = s.y / fmaxf(c.y, 1.0f) + b;
    o.z = s.z / fmaxf(c.z, 1.0f) + b;
    o.w = s.w / fmaxf(c.w, 1.0f) + b;
    ((float4*)out)[i4] = o;
    float4 z = make_float4(0.f, 0.f, 0.f, 0.f);
    *s4 = z;
    *c4 = z;
}

// Profiling-alignment nop: with 3 launches per call the fixed ncu capture
// (-s 5 -c 1) lands on the FIRST kernel of a call (verified R9/R11) = main.
__global__ void nop_kernel() {}

extern "C" void kernel_launch(void* const* d_in, const int* in_sizes, int n_in,
                              void* d_out, int out_size) {
    // Resolve inputs by element count (all distinct) — robust to metadata order.
    const float* feats = 0; const float* mats = 0;
    const int*   mask  = 0; const float* w_cls = 0; const float* b_cls = 0;
    for (int i = 0; i < n_in; i++) {
        switch (in_sizes[i]) {
            case 60211200: feats = (const float*)d_in[i]; break;
            case 96:       mats  = (const float*)d_in[i]; break;
            case 39200:    mask  = (const int*)d_in[i];   break;
            case 256:      w_cls = (const float*)d_in[i]; break;
            case 1:        b_cls = (const float*)d_in[i]; break;
            default: break;  // 156800 (lc) unused: meshgrid computed analytically
        }
    }
    float* out = (float*)d_out;

    dim3 grid((NPIX + 255) / 256, NCAM, NCHUNK);  // 154 x 6 x 4 = 3696 blocks
    bev_dot_scatter_kernel<<<grid, 256>>>(feats, mats, mask, w_cls);

    finalize_kernel<<<(NCELL / 4 + 255) / 256, 256>>>(out, b_cls);

    nop_kernel<<<1, 32>>>();
}